// round 7
// baseline (speedup 1.0000x reference)
#include <cuda_runtime.h>
#include <math.h>

#define Nn 4096
#define Dd 256
#define Kk 2048
#define MAXD 128
#define EPSc 1e-5f

// ---------------- scratch (device globals; no allocation) ----------------
__device__ float d_HN[Nn * Dd];        // normalized h
__device__ float d_P[Nn * Dd];         // per-node partial sums: P[k] = sum_{j in nbr(k)} SC[j]*HN[j]
__device__ float d_psum[64 * Dd];
__device__ float d_psq[64 * Dd];
__device__ float d_mu[Dd];
__device__ float d_inv[Dd];            // gamma / sqrt(var+eps)
__device__ int   d_nbr[Nn * MAXD];     // CSR neighbor lists
__device__ int   d_ncnt[Nn];
__device__ float d_deg[Nn];
__device__ float d_Z1[Nn];
__device__ float d_Z3[Nn];
__device__ float d_PF[Nn];
__device__ float d_SC[Nn];             // scores
__device__ int   d_idx[Kk];
__device__ unsigned d_selw[Nn / 32];   // bitmask of selected nodes
__device__ unsigned d_bm[Kk * (Nn / 32)]; // per-selected-row two-hop bitmaps (1 MB)
__device__ float d_rinv[Kk];           // 1 / rowcount(r)

// ---------------- K1: column stats (deterministic 2-stage) ----------------
__global__ void k_colstats(const float* __restrict__ h) {
    int b = blockIdx.x, d = threadIdx.x;
    float s = 0.f, q = 0.f;
    int r0 = b * 64;
    for (int r = 0; r < 64; r++) {
        float v = h[(r0 + r) * Dd + d];
        s += v; q += v * v;
    }
    d_psum[b * Dd + d] = s;
    d_psq [b * Dd + d] = q;
}

__global__ void k_colfin(const float* __restrict__ gamma) {
    int d = threadIdx.x;
    float s = 0.f, q = 0.f;
    for (int b = 0; b < 64; b++) { s += d_psum[b * Dd + d]; q += d_psq[b * Dd + d]; }
    float mu  = s / (float)Nn;
    float var = q / (float)Nn - mu * mu;
    d_mu[d]  = mu;
    d_inv[d] = gamma[d] / sqrtf(var + EPSc);
}

// ---------------- K2: normalize h (float4) ----------------
__global__ void k_norm(const float* __restrict__ h, const float* __restrict__ beta) {
    int t = blockIdx.x * blockDim.x + threadIdx.x;          // over Nn*Dd/4
    int d4 = t & (Dd / 4 - 1);
    float4 hv = ((const float4*)h)[t];
    float4 mu = ((const float4*)d_mu)[d4];
    float4 iv = ((const float4*)d_inv)[d4];
    float4 be = ((const float4*)beta)[d4];
    float4 o;
    o.x = (hv.x - mu.x) * iv.x + be.x;
    o.y = (hv.y - mu.y) * iv.y + be.y;
    o.z = (hv.z - mu.z) * iv.z + be.z;
    o.w = (hv.w - mu.w) * iv.w + be.w;
    ((float4*)d_HN)[t] = o;
}

// ---------------- K3: build CSR from dense binary g (warp/row, batched loads MLP=4) -------
__device__ __forceinline__ void csr_proc(float v, int col, int lane, unsigned lmask,
                                         int row, int& cnt) {
    unsigned m = __ballot_sync(0xffffffffu, v != 0.f);
    if (v != 0.f) {
        int p = cnt + __popc(m & lmask);
        if (p < MAXD) d_nbr[row * MAXD + p] = col;
    }
    cnt += __popc(m);
}

__global__ void k_csr(const float* __restrict__ g) {
    int row  = (blockIdx.x * blockDim.x + threadIdx.x) >> 5;
    int lane = threadIdx.x & 31;
    if (row >= Nn) return;
    const float4* r4 = (const float4*)(g + (size_t)row * Nn);
    unsigned lmask = (1u << lane) - 1u;
    int cnt = 0;
    for (int b = 0; b < 32; b += 4) {
        // 4 independent loads issued before the vote chain (MLP=4)
        float4 v0 = r4[(b + 0) * 32 + lane];
        float4 v1 = r4[(b + 1) * 32 + lane];
        float4 v2 = r4[(b + 2) * 32 + lane];
        float4 v3 = r4[(b + 3) * 32 + lane];
        int c0 = (b + 0) * 128 + lane * 4;
        csr_proc(v0.x, c0 + 0, lane, lmask, row, cnt);
        csr_proc(v0.y, c0 + 1, lane, lmask, row, cnt);
        csr_proc(v0.z, c0 + 2, lane, lmask, row, cnt);
        csr_proc(v0.w, c0 + 3, lane, lmask, row, cnt);
        int c1 = (b + 1) * 128 + lane * 4;
        csr_proc(v1.x, c1 + 0, lane, lmask, row, cnt);
        csr_proc(v1.y, c1 + 1, lane, lmask, row, cnt);
        csr_proc(v1.z, c1 + 2, lane, lmask, row, cnt);
        csr_proc(v1.w, c1 + 3, lane, lmask, row, cnt);
        int c2 = (b + 2) * 128 + lane * 4;
        csr_proc(v2.x, c2 + 0, lane, lmask, row, cnt);
        csr_proc(v2.y, c2 + 1, lane, lmask, row, cnt);
        csr_proc(v2.z, c2 + 2, lane, lmask, row, cnt);
        csr_proc(v2.w, c2 + 3, lane, lmask, row, cnt);
        int c3 = (b + 3) * 128 + lane * 4;
        csr_proc(v3.x, c3 + 0, lane, lmask, row, cnt);
        csr_proc(v3.y, c3 + 1, lane, lmask, row, cnt);
        csr_proc(v3.z, c3 + 2, lane, lmask, row, cnt);
        csr_proc(v3.w, c3 + 3, lane, lmask, row, cnt);
    }
    if (lane == 0) {
        d_ncnt[row] = cnt < MAXD ? cnt : MAXD;
        d_deg[row]  = (float)cnt;      // g is binary: sum == count
    }
}

// ---------------- K4: per-row agg, Z1, Z3, pf (single fused 3-value reduction) ----------
__global__ void k_rowfeat(const float* __restrict__ wproj, const float* __restrict__ bproj) {
    int i = blockIdx.x, d = threadIdx.x;
    __shared__ int   snb[MAXD];
    __shared__ float wr[8][3];
    int cnt = d_ncnt[i];
    if (d < cnt) snb[d] = d_nbr[i * MAXD + d];
    __syncthreads();
    float acc = 0.f;
    for (int e = 0; e < cnt; e++) acc += d_HN[snb[e] * Dd + d];
    float agg = acc / d_deg[i];
    float hv  = d_HN[i * Dd + d];
    float w   = wproj[d];
    float a = fabsf(hv - agg), b = agg * w, c = hv * w;
    for (int o = 16; o; o >>= 1) {
        a += __shfl_down_sync(0xffffffffu, a, o);
        b += __shfl_down_sync(0xffffffffu, b, o);
        c += __shfl_down_sync(0xffffffffu, c, o);
    }
    if ((d & 31) == 0) { wr[d >> 5][0] = a; wr[d >> 5][1] = b; wr[d >> 5][2] = c; }
    __syncthreads();
    if (d == 0) {
        float A = 0.f, B = 0.f, C = 0.f;
        for (int k = 0; k < 8; k++) { A += wr[k][0]; B += wr[k][1]; C += wr[k][2]; }
        float bb = bproj[0];
        d_Z1[i] = A;
        d_Z3[i] = B + bb;
        d_PF[i] = 1.f / (1.f + expf(-(C + bb)));
    }
}

// ---------------- K5: fused softmax + scores + exact top-k bitonic sort ----------------
__global__ void k_topk(const float* __restrict__ sigma1, float* __restrict__ out_idx) {
    __shared__ unsigned long long sk[Nn];
    __shared__ float sh[1024];
    int t = threadIdx.x;

    float mx = -3.4e38f;
    for (int i = t; i < Nn; i += 1024) mx = fmaxf(mx, d_Z3[i]);
    sh[t] = mx; __syncthreads();
    for (int s = 512; s > 0; s >>= 1) { if (t < s) sh[t] = fmaxf(sh[t], sh[t + s]); __syncthreads(); }
    float M = sh[0]; __syncthreads();
    float sm = 0.f;
    for (int i = t; i < Nn; i += 1024) sm += expf(d_Z3[i] - M);
    sh[t] = sm; __syncthreads();
    for (int s = 512; s > 0; s >>= 1) { if (t < s) sh[t] += sh[t + s]; __syncthreads(); }
    float S = sh[0];
    float s1 = sigma1[0];

    for (int i = t; i < Nn; i += 1024) {
        float pg = expf(d_Z3[i] - M) / S;
        float pl = 1.f / (1.f + expf(-(d_Z1[i] + d_deg[i])));
        float pt = 1.f / (1.f + expf(-(pl + pg)));
        float sc = s1 * pt + (1.f - s1) * d_PF[i];
        d_SC[i] = sc;
        unsigned u = __float_as_uint(sc);
        u = (u & 0x80000000u) ? ~u : (u | 0x80000000u);
        sk[i] = ((unsigned long long)(~u) << 32) | (unsigned)i;  // asc key = desc score, asc idx ties
    }
    if (t < Nn / 32) d_selw[t] = 0u;
    __syncthreads();

    for (int k = 2; k <= Nn; k <<= 1) {
        for (int j = k >> 1; j > 0; j >>= 1) {
            for (int i = t; i < Nn; i += 1024) {
                int ixj = i ^ j;
                if (ixj > i) {
                    bool up = ((i & k) == 0);
                    unsigned long long a = sk[i], b = sk[ixj];
                    if ((a > b) == up) { sk[i] = b; sk[ixj] = a; }
                }
            }
            __syncthreads();
        }
    }
    for (int c = t; c < Kk; c += 1024) {
        int j = (int)(sk[c] & 0xffffffffULL);
        d_idx[c] = j;
        atomicOr(&d_selw[j >> 5], 1u << (j & 31));
        out_idx[c] = (float)j;
    }
}

// ---------------- K6: P[k] = sum_{j in nbr(k)} SC[j]*HN[j]  (all 4096 nodes) -------------
__global__ void k_pbuild() {
    __shared__ int   snb[MAXD];
    __shared__ float4 red[3][64];
    int k = blockIdx.x, d = threadIdx.x;
    int cnt = d_ncnt[k];
    if (d < cnt) snb[d] = d_nbr[k * MAXD + d];
    __syncthreads();
    int grp = d >> 6, l = d & 63;
    const float4* HN4 = (const float4*)d_HN;
    float4 acc = make_float4(0.f, 0.f, 0.f, 0.f);
    for (int e = grp; e < cnt; e += 4) {
        int j = snb[e];
        float s = d_SC[j];
        float4 v = HN4[j * 64 + l];
        acc.x += s * v.x; acc.y += s * v.y; acc.z += s * v.z; acc.w += s * v.w;
    }
    if (grp > 0) red[grp - 1][l] = acc;
    __syncthreads();
    if (grp == 0) {
        for (int q = 0; q < 3; q++) {
            float4 v = red[q][l];
            acc.x += v.x; acc.y += v.y; acc.z += v.z; acc.w += v.w;
        }
        ((float4*)d_P)[k * 64 + l] = acc;
    }
}

// ---------------- K7: per-selected-row: multiplicity counts -> new_h via P-sums ----------
__global__ void k_pool(float* __restrict__ out_newh) {
    __shared__ int cnt[Nn];            // 16 KB multiplicity counters
    __shared__ int snb[MAXD];
    __shared__ int dupj[512];
    __shared__ int dupm[512];
    __shared__ int ndup_s;
    __shared__ float4 red[3][64];
    __shared__ int redi[256];
    int r = blockIdx.x, d = threadIdx.x;
    int i = d_idx[r];
    for (int w = d; w < Nn; w += 256) cnt[w] = 0;
    int c1 = d_ncnt[i];
    if (d < c1) snb[d] = d_nbr[i * MAXD + d];
    __syncthreads();

    // multiplicity counting over 1-hop neighborhood expansions
    for (int e = d; e < c1; e += 256) {
        int k = snb[e];
        int c2 = d_ncnt[k];
        const int* nb = &d_nbr[k * MAXD];
        for (int f = 0; f < c2; f++) atomicAdd(&cnt[nb[f]], 1);
    }
    __syncthreads();

    // bitmap + selected-count
    int csel = 0;
    if (d < Nn / 32) {
        unsigned w = 0u;
        int base = d * 32;
        for (int b = 0; b < 32; b++) if (cnt[base + b]) w |= (1u << b);
        d_bm[r * (Nn / 32) + d] = w;
        csel = __popc(w & d_selw[d]);
    }
    redi[d] = csel;
    __syncthreads();
    for (int s = 128; s > 0; s >>= 1) { if (d < s) redi[d] += redi[d + s]; __syncthreads(); }
    if (d == 0) d_rinv[r] = 1.f / (float)redi[0];

    // warp 0 builds ordered duplicate list (j with cnt>1, ascending)
    if (d < 32) {
        int off = 0;
        unsigned lm = (1u << d) - 1u;
        for (int base = 0; base < Nn / 32; base++) {
            int j = base * 32 + d;
            int m = cnt[j];
            unsigned bal = __ballot_sync(0xffffffffu, m > 1);
            if (m > 1) {
                int p = off + __popc(bal & lm);
                dupj[p] = j;
                dupm[p] = m - 1;
            }
            off += __popc(bal);
        }
        if (d == 0) ndup_s = off;
    }
    __syncthreads();
    int nd = ndup_s;

    // new_h[r] = sum_k P[k]  -  sum_dup (mult-1)*SC[j]*HN[j]
    int grp = d >> 6, l = d & 63;
    const float4* P4  = (const float4*)d_P;
    const float4* HN4 = (const float4*)d_HN;
    float4 acc = make_float4(0.f, 0.f, 0.f, 0.f);
    for (int e = grp; e < c1; e += 4) {
        int k = snb[e];
        float4 v = P4[k * 64 + l];
        acc.x += v.x; acc.y += v.y; acc.z += v.z; acc.w += v.w;
    }
    for (int e = grp; e < nd; e += 4) {
        int j = dupj[e];
        float s = (float)dupm[e] * d_SC[j];
        float4 v = HN4[j * 64 + l];
        acc.x -= s * v.x; acc.y -= s * v.y; acc.z -= s * v.z; acc.w -= s * v.w;
    }
    if (grp > 0) red[grp - 1][l] = acc;
    __syncthreads();
    if (grp == 0) {
        for (int q = 0; q < 3; q++) {
            float4 v = red[q][l];
            acc.x += v.x; acc.y += v.y; acc.z += v.z; acc.w += v.w;
        }
        ((float4*)out_newh)[(size_t)r * 64 + l] = acc;
    }
}

// ---------------- K8: write g_new directly (membership bit * column rinv) ----------------
__global__ void k_gnew(float* __restrict__ out_gnew) {
    int t = blockIdx.x * blockDim.x + threadIdx.x;
    int r = t >> 11, c = t & (Kk - 1);
    int j = d_idx[c];
    unsigned w = d_bm[r * (Nn / 32) + (j >> 5)];
    out_gnew[t] = ((w >> (j & 31)) & 1u) ? d_rinv[c] : 0.f;
}

// ---------------- launch ----------------
extern "C" void kernel_launch(void* const* d_in, const int* in_sizes, int n_in,
                              void* d_out, int out_size) {
    const float* g      = (const float*)d_in[0];
    const float* h      = (const float*)d_in[1];
    const float* gamma  = (const float*)d_in[2];
    const float* beta   = (const float*)d_in[3];
    const float* wproj  = (const float*)d_in[4];
    const float* bproj  = (const float*)d_in[5];
    const float* sigma1 = (const float*)d_in[6];

    float* out      = (float*)d_out;
    float* out_gnew = out;                               // Kk*Kk
    float* out_newh = out + (size_t)Kk * Kk;             // Kk*Dd
    float* out_idx  = out_newh + (size_t)Kk * Dd;        // Kk

    k_colstats<<<64, 256>>>(h);
    k_colfin  <<<1, 256>>>(gamma);
    k_norm    <<<(Nn * Dd / 4) / 256, 256>>>(h, beta);
    k_csr     <<<Nn / 8, 256>>>(g);
    k_rowfeat <<<Nn, 256>>>(wproj, bproj);
    k_topk    <<<1, 1024>>>(sigma1, out_idx);
    k_pbuild  <<<Nn, 256>>>();
    k_pool    <<<Kk, 256>>>(out_newh);
    k_gnew    <<<(Kk * Kk) / 256, 256>>>(out_gnew);
}

// round 8
// speedup vs baseline: 1.3242x; 1.3242x over previous
#include <cuda_runtime.h>
#include <cuda_fp16.h>
#include <math.h>

#define Nn 4096
#define Dd 256
#define Kk 2048
#define MAXD 128
#define EPSc 1e-5f

// ---------------- scratch (device globals; no allocation) ----------------
__device__ float  d_HN[Nn * Dd];        // normalized h (fp32, score path)
__device__ __half d_HNh[Nn * Dd];       // fp16 mirror (gather path only)
__device__ float  d_psum[64 * Dd];
__device__ float  d_psq[64 * Dd];
__device__ float  d_mu[Dd];
__device__ float  d_inv[Dd];            // gamma / sqrt(var+eps)
__device__ int    d_nbr[Nn * MAXD];     // CSR neighbor lists
__device__ int    d_ncnt[Nn];
__device__ float  d_deg[Nn];
__device__ float  d_Z1[Nn];
__device__ float  d_Z3[Nn];
__device__ float  d_PF[Nn];
__device__ float  d_SC[Nn];             // scores
__device__ int    d_idx[Kk];
__device__ unsigned d_selw[Nn / 32];    // bitmask of selected nodes
__device__ unsigned d_bm[Kk * (Nn / 32)]; // per-selected-row two-hop bitmaps (1 MB)
__device__ float  d_rinv[Kk];           // 1 / rowcount(r)

// ---------------- K1: column stats (deterministic 2-stage) ----------------
__global__ void k_colstats(const float* __restrict__ h) {
    int b = blockIdx.x, d = threadIdx.x;
    float s = 0.f, q = 0.f;
    int r0 = b * 64;
    for (int r = 0; r < 64; r++) {
        float v = h[(r0 + r) * Dd + d];
        s += v; q += v * v;
    }
    d_psum[b * Dd + d] = s;
    d_psq [b * Dd + d] = q;
}

__global__ void k_colfin(const float* __restrict__ gamma) {
    int d = threadIdx.x;
    float s = 0.f, q = 0.f;
    for (int b = 0; b < 64; b++) { s += d_psum[b * Dd + d]; q += d_psq[b * Dd + d]; }
    float mu  = s / (float)Nn;
    float var = q / (float)Nn - mu * mu;
    d_mu[d]  = mu;
    d_inv[d] = gamma[d] / sqrtf(var + EPSc);
}

// ---------------- K2: normalize h (float4), write fp32 + fp16 mirror ----------------
__global__ void k_norm(const float* __restrict__ h, const float* __restrict__ beta) {
    int t = blockIdx.x * blockDim.x + threadIdx.x;          // over Nn*Dd/4
    int d4 = t & (Dd / 4 - 1);
    float4 hv = ((const float4*)h)[t];
    float4 mu = ((const float4*)d_mu)[d4];
    float4 iv = ((const float4*)d_inv)[d4];
    float4 be = ((const float4*)beta)[d4];
    float4 o;
    o.x = (hv.x - mu.x) * iv.x + be.x;
    o.y = (hv.y - mu.y) * iv.y + be.y;
    o.z = (hv.z - mu.z) * iv.z + be.z;
    o.w = (hv.w - mu.w) * iv.w + be.w;
    ((float4*)d_HN)[t] = o;
    __half2 p0 = __floats2half2_rn(o.x, o.y);
    __half2 p1 = __floats2half2_rn(o.z, o.w);
    ((__half2*)d_HNh)[t * 2 + 0] = p0;
    ((__half2*)d_HNh)[t * 2 + 1] = p1;
}

// ---------------- K3: CSR from dense binary g (warp/row; batched independent ballots) ----
__global__ void k_csr(const float* __restrict__ g) {
    int row  = (blockIdx.x * blockDim.x + threadIdx.x) >> 5;
    int lane = threadIdx.x & 31;
    if (row >= Nn) return;
    const float4* r4 = (const float4*)(g + (size_t)row * Nn);
    unsigned lmask = (1u << lane) - 1u;
    int cnt = 0;
    for (int b = 0; b < 32; b += 4) {
        // 4 independent 16B loads (MLP=4)
        float4 v0 = r4[(b + 0) * 32 + lane];
        float4 v1 = r4[(b + 1) * 32 + lane];
        float4 v2 = r4[(b + 2) * 32 + lane];
        float4 v3 = r4[(b + 3) * 32 + lane];
        float va[16];
        va[0]=v0.x; va[1]=v0.y; va[2]=v0.z; va[3]=v0.w;
        va[4]=v1.x; va[5]=v1.y; va[6]=v1.z; va[7]=v1.w;
        va[8]=v2.x; va[9]=v2.y; va[10]=v2.z; va[11]=v2.w;
        va[12]=v3.x; va[13]=v3.y; va[14]=v3.z; va[15]=v3.w;
        unsigned m[16];
        #pragma unroll
        for (int q = 0; q < 16; q++) m[q] = __ballot_sync(0xffffffffu, va[q] != 0.f);
        int off = cnt;
        int cbase = b * 128 + lane * 4;
        #pragma unroll
        for (int q = 0; q < 16; q++) {
            if (va[q] != 0.f) {
                int p = off + __popc(m[q] & lmask);
                if (p < MAXD) d_nbr[row * MAXD + p] = cbase + (q >> 2) * 128 + (q & 3);
            }
            off += __popc(m[q]);
        }
        cnt = off;
    }
    if (lane == 0) {
        d_ncnt[row] = cnt < MAXD ? cnt : MAXD;
        d_deg[row]  = (float)cnt;      // g is binary: sum == count
    }
}

// ---------------- K4: per-row agg, Z1, Z3, pf (single fused 3-value reduction) ----------
__global__ void k_rowfeat(const float* __restrict__ wproj, const float* __restrict__ bproj) {
    int i = blockIdx.x, d = threadIdx.x;
    __shared__ int   snb[MAXD];
    __shared__ float wr[8][3];
    int cnt = d_ncnt[i];
    if (d < cnt) snb[d] = d_nbr[i * MAXD + d];
    __syncthreads();
    float acc = 0.f;
    for (int e = 0; e < cnt; e++) acc += d_HN[snb[e] * Dd + d];
    float agg = acc / d_deg[i];
    float hv  = d_HN[i * Dd + d];
    float w   = wproj[d];
    float a = fabsf(hv - agg), b = agg * w, c = hv * w;
    for (int o = 16; o; o >>= 1) {
        a += __shfl_down_sync(0xffffffffu, a, o);
        b += __shfl_down_sync(0xffffffffu, b, o);
        c += __shfl_down_sync(0xffffffffu, c, o);
    }
    if ((d & 31) == 0) { wr[d >> 5][0] = a; wr[d >> 5][1] = b; wr[d >> 5][2] = c; }
    __syncthreads();
    if (d == 0) {
        float A = 0.f, B = 0.f, C = 0.f;
        for (int k = 0; k < 8; k++) { A += wr[k][0]; B += wr[k][1]; C += wr[k][2]; }
        float bb = bproj[0];
        d_Z1[i] = A;
        d_Z3[i] = B + bb;
        d_PF[i] = 1.f / (1.f + expf(-(C + bb)));
    }
}

// ---------------- K5: fused softmax + scores + exact top-k bitonic sort ----------------
__global__ void k_topk(const float* __restrict__ sigma1, float* __restrict__ out_idx) {
    __shared__ unsigned long long sk[Nn];
    __shared__ float sh[1024];
    int t = threadIdx.x;

    float mx = -3.4e38f;
    for (int i = t; i < Nn; i += 1024) mx = fmaxf(mx, d_Z3[i]);
    sh[t] = mx; __syncthreads();
    for (int s = 512; s > 0; s >>= 1) { if (t < s) sh[t] = fmaxf(sh[t], sh[t + s]); __syncthreads(); }
    float M = sh[0]; __syncthreads();
    float sm = 0.f;
    for (int i = t; i < Nn; i += 1024) sm += expf(d_Z3[i] - M);
    sh[t] = sm; __syncthreads();
    for (int s = 512; s > 0; s >>= 1) { if (t < s) sh[t] += sh[t + s]; __syncthreads(); }
    float S = sh[0];
    float s1 = sigma1[0];

    for (int i = t; i < Nn; i += 1024) {
        float pg = expf(d_Z3[i] - M) / S;
        float pl = 1.f / (1.f + expf(-(d_Z1[i] + d_deg[i])));
        float pt = 1.f / (1.f + expf(-(pl + pg)));
        float sc = s1 * pt + (1.f - s1) * d_PF[i];
        d_SC[i] = sc;
        unsigned u = __float_as_uint(sc);
        u = (u & 0x80000000u) ? ~u : (u | 0x80000000u);
        sk[i] = ((unsigned long long)(~u) << 32) | (unsigned)i;  // asc key = desc score, asc idx ties
    }
    if (t < Nn / 32) d_selw[t] = 0u;
    __syncthreads();

    for (int k = 2; k <= Nn; k <<= 1) {
        for (int j = k >> 1; j > 0; j >>= 1) {
            for (int i = t; i < Nn; i += 1024) {
                int ixj = i ^ j;
                if (ixj > i) {
                    bool up = ((i & k) == 0);
                    unsigned long long a = sk[i], b = sk[ixj];
                    if ((a > b) == up) { sk[i] = b; sk[ixj] = a; }
                }
            }
            __syncthreads();
        }
    }
    for (int c = t; c < Kk; c += 1024) {
        int j = (int)(sk[c] & 0xffffffffULL);
        d_idx[c] = j;
        atomicOr(&d_selw[j >> 5], 1u << (j & 31));
        out_idx[c] = (float)j;
    }
}

// ---------------- K6: per-selected-row two-hop -> new_h (fp16 gather), bitmap, rowcount ---
__global__ void k_pool(float* __restrict__ out_newh) {
    __shared__ unsigned bm[Nn / 32];
    __shared__ int scn[Nn / 32];
    __shared__ int list[Nn];
    __shared__ float red[7][32][8];
    __shared__ int redi[256];
    int r = blockIdx.x, d = threadIdx.x;
    int i = d_idx[r];
    if (d < Nn / 32) bm[d] = 0u;
    __syncthreads();

    // two-hop expansion into bitmap
    int c1 = d_ncnt[i];
    for (int e = d; e < c1; e += 256) {
        int k = d_nbr[i * MAXD + e];
        int c2 = d_ncnt[k];
        const int* nb = &d_nbr[k * MAXD];
        for (int f = 0; f < c2; f++) {
            int j = nb[f];
            atomicOr(&bm[j >> 5], 1u << (j & 31));
        }
    }
    __syncthreads();

    // deterministic ordered extraction via prefix scan over 128 words
    int pc = (d < Nn / 32) ? __popc(bm[d]) : 0;
    if (d < Nn / 32) scn[d] = pc;
    __syncthreads();
    for (int off = 1; off < Nn / 32; off <<= 1) {
        int v = 0;
        if (d < Nn / 32) { v = scn[d]; if (d >= off) v += scn[d - off]; }
        __syncthreads();
        if (d < Nn / 32) scn[d] = v;
        __syncthreads();
    }
    if (d < Nn / 32) {
        int p = scn[d] - pc;
        unsigned v = bm[d];
        while (v) { int b = __ffs((int)v) - 1; v &= v - 1; list[p++] = d * 32 + b; }
        d_bm[r * (Nn / 32) + d] = bm[d];           // persist bitmap for k_gnew
    }
    // selected-in-row count -> rinv
    int csel = (d < Nn / 32) ? __popc(bm[d] & d_selw[d]) : 0;
    redi[d] = csel;
    __syncthreads();
    int m = scn[Nn / 32 - 1];
    for (int s = 128; s > 0; s >>= 1) { if (d < s) redi[d] += redi[d + s]; __syncthreads(); }
    if (d == 0) d_rinv[r] = 1.f / (float)redi[0];

    // new_h[r] = sum_j SC[j]*HN[j] ; fp16 gather: 8 groups x 32 lanes, 8 dims/lane (uint4)
    int grp = d >> 5, l = d & 31;
    const uint4* H4 = (const uint4*)d_HNh;         // 16B = 8 halves
    float acc[8];
    #pragma unroll
    for (int q = 0; q < 8; q++) acc[q] = 0.f;
    for (int e = grp; e < m; e += 8) {
        int j = list[e];
        float s = d_SC[j];
        uint4 v = H4[j * 32 + l];
        const __half2* hp = (const __half2*)&v;
        float2 f0 = __half22float2(hp[0]);
        float2 f1 = __half22float2(hp[1]);
        float2 f2 = __half22float2(hp[2]);
        float2 f3 = __half22float2(hp[3]);
        acc[0] += s * f0.x; acc[1] += s * f0.y;
        acc[2] += s * f1.x; acc[3] += s * f1.y;
        acc[4] += s * f2.x; acc[5] += s * f2.y;
        acc[6] += s * f3.x; acc[7] += s * f3.y;
    }
    if (grp > 0) {
        #pragma unroll
        for (int q = 0; q < 8; q++) red[grp - 1][l][q] = acc[q];
    }
    __syncthreads();
    if (grp == 0) {
        #pragma unroll
        for (int gq = 0; gq < 7; gq++)
            #pragma unroll
            for (int q = 0; q < 8; q++) acc[q] += red[gq][l][q];
        float4 o0 = make_float4(acc[0], acc[1], acc[2], acc[3]);
        float4 o1 = make_float4(acc[4], acc[5], acc[6], acc[7]);
        ((float4*)out_newh)[(size_t)r * 64 + l * 2 + 0] = o0;
        ((float4*)out_newh)[(size_t)r * 64 + l * 2 + 1] = o1;
    }
}

// ---------------- K7: write g_new directly (membership bit * column rinv) ----------------
__global__ void k_gnew(float* __restrict__ out_gnew) {
    int t = blockIdx.x * blockDim.x + threadIdx.x;
    int r = t >> 11, c = t & (Kk - 1);
    int j = d_idx[c];
    unsigned w = d_bm[r * (Nn / 32) + (j >> 5)];
    out_gnew[t] = ((w >> (j & 31)) & 1u) ? d_rinv[c] : 0.f;
}

// ---------------- launch ----------------
extern "C" void kernel_launch(void* const* d_in, const int* in_sizes, int n_in,
                              void* d_out, int out_size) {
    const float* g      = (const float*)d_in[0];
    const float* h      = (const float*)d_in[1];
    const float* gamma  = (const float*)d_in[2];
    const float* beta   = (const float*)d_in[3];
    const float* wproj  = (const float*)d_in[4];
    const float* bproj  = (const float*)d_in[5];
    const float* sigma1 = (const float*)d_in[6];

    float* out      = (float*)d_out;
    float* out_gnew = out;                               // Kk*Kk
    float* out_newh = out + (size_t)Kk * Kk;             // Kk*Dd
    float* out_idx  = out_newh + (size_t)Kk * Dd;        // Kk

    k_csr     <<<Nn / 8, 256>>>(g);     // big streaming scan first (L2 hygiene)
    k_colstats<<<64, 256>>>(h);
    k_colfin  <<<1, 256>>>(gamma);
    k_norm    <<<(Nn * Dd / 4) / 256, 256>>>(h, beta);
    k_rowfeat <<<Nn, 256>>>(wproj, bproj);
    k_topk    <<<1, 1024>>>(sigma1, out_idx);
    k_pool    <<<Kk, 256>>>(out_newh);
    k_gnew    <<<(Kk * Kk) / 256, 256>>>(out_gnew);
}

// round 9
// speedup vs baseline: 1.4064x; 1.0621x over previous
#include <cuda_runtime.h>
#include <cuda_fp16.h>
#include <math.h>

#define Nn 4096
#define Dd 256
#define Kk 2048
#define MAXD 128
#define EPSc 1e-5f

// ---------------- scratch (device globals; no allocation) ----------------
__device__ float  d_HN[Nn * Dd];        // normalized h (fp32, score path)
__device__ __half d_HNh[Nn * Dd];       // fp16 mirror (gather path only)
__device__ float  d_psum[64 * Dd];
__device__ float  d_psq[64 * Dd];
__device__ float  d_mu[Dd];
__device__ float  d_inv[Dd];            // gamma / sqrt(var+eps)
__device__ int    d_nbr[Nn * MAXD];     // CSR neighbor lists (fixed lane-interleaved order)
__device__ int    d_ncnt[Nn];
__device__ float  d_deg[Nn];
__device__ float  d_Z1[Nn];
__device__ float  d_Z3[Nn];
__device__ float  d_PF[Nn];
__device__ float  d_SC[Nn];             // scores
__device__ int    d_idx[Kk];
__device__ unsigned d_selw[Nn / 32];    // bitmask of selected nodes
__device__ unsigned d_bm[Kk * (Nn / 32)]; // per-selected-row two-hop bitmaps (1 MB)
__device__ float  d_rinv[Kk];           // 1 / rowcount(r)

// ---------------- K1: column stats (deterministic 2-stage) ----------------
__global__ void k_colstats(const float* __restrict__ h) {
    int b = blockIdx.x, d = threadIdx.x;
    float s = 0.f, q = 0.f;
    int r0 = b * 64;
    for (int r = 0; r < 64; r++) {
        float v = h[(r0 + r) * Dd + d];
        s += v; q += v * v;
    }
    d_psum[b * Dd + d] = s;
    d_psq [b * Dd + d] = q;
}

__global__ void k_colfin(const float* __restrict__ gamma) {
    int d = threadIdx.x;
    float s = 0.f, q = 0.f;
    for (int b = 0; b < 64; b++) { s += d_psum[b * Dd + d]; q += d_psq[b * Dd + d]; }
    float mu  = s / (float)Nn;
    float var = q / (float)Nn - mu * mu;
    d_mu[d]  = mu;
    d_inv[d] = gamma[d] / sqrtf(var + EPSc);
}

// ---------------- K2: normalize h (float4), write fp32 + fp16 mirror ----------------
__global__ void k_norm(const float* __restrict__ h, const float* __restrict__ beta) {
    int t = blockIdx.x * blockDim.x + threadIdx.x;          // over Nn*Dd/4
    int d4 = t & (Dd / 4 - 1);
    float4 hv = ((const float4*)h)[t];
    float4 mu = ((const float4*)d_mu)[d4];
    float4 iv = ((const float4*)d_inv)[d4];
    float4 be = ((const float4*)beta)[d4];
    float4 o;
    o.x = (hv.x - mu.x) * iv.x + be.x;
    o.y = (hv.y - mu.y) * iv.y + be.y;
    o.z = (hv.z - mu.z) * iv.z + be.z;
    o.w = (hv.w - mu.w) * iv.w + be.w;
    ((float4*)d_HN)[t] = o;
    __half2 p0 = __floats2half2_rn(o.x, o.y);
    __half2 p1 = __floats2half2_rn(o.z, o.w);
    ((__half2*)d_HNh)[t * 2 + 0] = p0;
    ((__half2*)d_HNh)[t * 2 + 1] = p1;
}

// ---------------- K3: CSR from dense binary g (warp/row; per-lane masks + 1 scan/batch) --
__global__ void k_csr(const float* __restrict__ g) {
    int row  = (blockIdx.x * blockDim.x + threadIdx.x) >> 5;
    int lane = threadIdx.x & 31;
    if (row >= Nn) return;
    const float4* r4 = (const float4*)(g + (size_t)row * Nn);
    int cnt = 0;
    for (int b = 0; b < 8; b++) {
        // 4 independent 16B loads (MLP=4)
        float4 v0 = r4[(b * 4 + 0) * 32 + lane];
        float4 v1 = r4[(b * 4 + 1) * 32 + lane];
        float4 v2 = r4[(b * 4 + 2) * 32 + lane];
        float4 v3 = r4[(b * 4 + 3) * 32 + lane];
        unsigned msk = 0u;
        msk |= (v0.x != 0.f) ? 0x0001u : 0u;  msk |= (v0.y != 0.f) ? 0x0002u : 0u;
        msk |= (v0.z != 0.f) ? 0x0004u : 0u;  msk |= (v0.w != 0.f) ? 0x0008u : 0u;
        msk |= (v1.x != 0.f) ? 0x0010u : 0u;  msk |= (v1.y != 0.f) ? 0x0020u : 0u;
        msk |= (v1.z != 0.f) ? 0x0040u : 0u;  msk |= (v1.w != 0.f) ? 0x0080u : 0u;
        msk |= (v2.x != 0.f) ? 0x0100u : 0u;  msk |= (v2.y != 0.f) ? 0x0200u : 0u;
        msk |= (v2.z != 0.f) ? 0x0400u : 0u;  msk |= (v2.w != 0.f) ? 0x0800u : 0u;
        msk |= (v3.x != 0.f) ? 0x1000u : 0u;  msk |= (v3.y != 0.f) ? 0x2000u : 0u;
        msk |= (v3.z != 0.f) ? 0x4000u : 0u;  msk |= (v3.w != 0.f) ? 0x8000u : 0u;
        int lc = __popc(msk);
        // warp inclusive scan of lc (5 shfls), then exclusive base
        int inc = lc;
        #pragma unroll
        for (int o = 1; o < 32; o <<= 1) {
            int n = __shfl_up_sync(0xffffffffu, inc, o);
            if (lane >= o) inc += n;
        }
        int total = __shfl_sync(0xffffffffu, inc, 31);
        int base = cnt + inc - lc;
        while (msk) {
            int q = __ffs((int)msk) - 1;
            msk &= msk - 1;
            int col = (b * 4 + (q >> 2)) * 128 + lane * 4 + (q & 3);
            if (base < MAXD) d_nbr[row * MAXD + base] = col;
            base++;
        }
        cnt += total;
    }
    if (lane == 0) {
        d_ncnt[row] = cnt < MAXD ? cnt : MAXD;
        d_deg[row]  = (float)cnt;      // g is binary: sum == count
    }
}

// ---------------- K4: per-row agg, Z1, Z3, pf (single fused 3-value reduction) ----------
__global__ void k_rowfeat(const float* __restrict__ wproj, const float* __restrict__ bproj) {
    int i = blockIdx.x, d = threadIdx.x;
    __shared__ int   snb[MAXD];
    __shared__ float wr[8][3];
    int cnt = d_ncnt[i];
    if (d < cnt) snb[d] = d_nbr[i * MAXD + d];
    __syncthreads();
    float acc = 0.f;
    for (int e = 0; e < cnt; e++) acc += d_HN[snb[e] * Dd + d];
    float agg = acc / d_deg[i];
    float hv  = d_HN[i * Dd + d];
    float w   = wproj[d];
    float a = fabsf(hv - agg), b = agg * w, c = hv * w;
    for (int o = 16; o; o >>= 1) {
        a += __shfl_down_sync(0xffffffffu, a, o);
        b += __shfl_down_sync(0xffffffffu, b, o);
        c += __shfl_down_sync(0xffffffffu, c, o);
    }
    if ((d & 31) == 0) { wr[d >> 5][0] = a; wr[d >> 5][1] = b; wr[d >> 5][2] = c; }
    __syncthreads();
    if (d == 0) {
        float A = 0.f, B = 0.f, C = 0.f;
        for (int k = 0; k < 8; k++) { A += wr[k][0]; B += wr[k][1]; C += wr[k][2]; }
        float bb = bproj[0];
        d_Z1[i] = A;
        d_Z3[i] = B + bb;
        d_PF[i] = 1.f / (1.f + expf(-(C + bb)));
    }
}

// ---------------- K5: fused softmax + scores + exact top-k bitonic sort ----------------
__global__ void k_topk(const float* __restrict__ sigma1, float* __restrict__ out_idx) {
    __shared__ unsigned long long sk[Nn];
    __shared__ float sh[1024];
    int t = threadIdx.x;

    float mx = -3.4e38f;
    for (int i = t; i < Nn; i += 1024) mx = fmaxf(mx, d_Z3[i]);
    sh[t] = mx; __syncthreads();
    for (int s = 512; s > 0; s >>= 1) { if (t < s) sh[t] = fmaxf(sh[t], sh[t + s]); __syncthreads(); }
    float M = sh[0]; __syncthreads();
    float sm = 0.f;
    for (int i = t; i < Nn; i += 1024) sm += expf(d_Z3[i] - M);
    sh[t] = sm; __syncthreads();
    for (int s = 512; s > 0; s >>= 1) { if (t < s) sh[t] += sh[t + s]; __syncthreads(); }
    float S = sh[0];
    float s1 = sigma1[0];

    for (int i = t; i < Nn; i += 1024) {
        float pg = expf(d_Z3[i] - M) / S;
        float pl = 1.f / (1.f + expf(-(d_Z1[i] + d_deg[i])));
        float pt = 1.f / (1.f + expf(-(pl + pg)));
        float sc = s1 * pt + (1.f - s1) * d_PF[i];
        d_SC[i] = sc;
        unsigned u = __float_as_uint(sc);
        u = (u & 0x80000000u) ? ~u : (u | 0x80000000u);
        sk[i] = ((unsigned long long)(~u) << 32) | (unsigned)i;  // asc key = desc score, asc idx ties
    }
    if (t < Nn / 32) d_selw[t] = 0u;
    __syncthreads();

    for (int k = 2; k <= Nn; k <<= 1) {
        for (int j = k >> 1; j > 0; j >>= 1) {
            for (int i = t; i < Nn; i += 1024) {
                int ixj = i ^ j;
                if (ixj > i) {
                    bool up = ((i & k) == 0);
                    unsigned long long a = sk[i], b = sk[ixj];
                    if ((a > b) == up) { sk[i] = b; sk[ixj] = a; }
                }
            }
            __syncthreads();
        }
    }
    for (int c = t; c < Kk; c += 1024) {
        int j = (int)(sk[c] & 0xffffffffULL);
        d_idx[c] = j;
        atomicOr(&d_selw[j >> 5], 1u << (j & 31));
        out_idx[c] = (float)j;
    }
}

// ---------------- K6: per-selected-row two-hop -> new_h (fp16 gather), bitmap, rowcount ---
__global__ void k_pool(float* __restrict__ out_newh) {
    __shared__ unsigned bm[Nn / 32];
    __shared__ int scn[Nn / 32];
    __shared__ int list[Nn];
    __shared__ float red[7][32][8];
    __shared__ int redi[256];
    int r = blockIdx.x, d = threadIdx.x;
    int i = d_idx[r];
    if (d < Nn / 32) bm[d] = 0u;
    __syncthreads();

    // two-hop expansion into bitmap
    int c1 = d_ncnt[i];
    for (int e = d; e < c1; e += 256) {
        int k = d_nbr[i * MAXD + e];
        int c2 = d_ncnt[k];
        const int* nb = &d_nbr[k * MAXD];
        for (int f = 0; f < c2; f++) {
            int j = nb[f];
            atomicOr(&bm[j >> 5], 1u << (j & 31));
        }
    }
    __syncthreads();

    // deterministic ordered extraction via prefix scan over 128 words
    int pc = (d < Nn / 32) ? __popc(bm[d]) : 0;
    if (d < Nn / 32) scn[d] = pc;
    __syncthreads();
    for (int off = 1; off < Nn / 32; off <<= 1) {
        int v = 0;
        if (d < Nn / 32) { v = scn[d]; if (d >= off) v += scn[d - off]; }
        __syncthreads();
        if (d < Nn / 32) scn[d] = v;
        __syncthreads();
    }
    if (d < Nn / 32) {
        int p = scn[d] - pc;
        unsigned v = bm[d];
        while (v) { int b = __ffs((int)v) - 1; v &= v - 1; list[p++] = d * 32 + b; }
        d_bm[r * (Nn / 32) + d] = bm[d];           // persist bitmap for k_gnew
    }
    // selected-in-row count -> rinv
    int csel = (d < Nn / 32) ? __popc(bm[d] & d_selw[d]) : 0;
    redi[d] = csel;
    __syncthreads();
    int m = scn[Nn / 32 - 1];
    for (int s = 128; s > 0; s >>= 1) { if (d < s) redi[d] += redi[d + s]; __syncthreads(); }
    if (d == 0) d_rinv[r] = 1.f / (float)redi[0];

    // new_h[r] = sum_j SC[j]*HN[j] ; fp16 gather: 8 groups x 32 lanes, 8 dims/lane (uint4)
    // unroll-by-2 with dual accumulators for MLP
    int grp = d >> 5, l = d & 31;
    const uint4* H4 = (const uint4*)d_HNh;         // 16B = 8 halves
    float accA[8], accB[8];
    #pragma unroll
    for (int q = 0; q < 8; q++) { accA[q] = 0.f; accB[q] = 0.f; }
    int e = grp;
    for (; e + 8 < m; e += 16) {
        int j0 = list[e], j1 = list[e + 8];
        float s0 = d_SC[j0], s1 = d_SC[j1];
        uint4 va = H4[j0 * 32 + l];
        uint4 vb = H4[j1 * 32 + l];
        const __half2* ha = (const __half2*)&va;
        const __half2* hb = (const __half2*)&vb;
        #pragma unroll
        for (int q = 0; q < 4; q++) {
            float2 fa = __half22float2(ha[q]);
            float2 fb = __half22float2(hb[q]);
            accA[q * 2 + 0] += s0 * fa.x; accA[q * 2 + 1] += s0 * fa.y;
            accB[q * 2 + 0] += s1 * fb.x; accB[q * 2 + 1] += s1 * fb.y;
        }
    }
    for (; e < m; e += 8) {
        int j = list[e];
        float s = d_SC[j];
        uint4 v = H4[j * 32 + l];
        const __half2* hp = (const __half2*)&v;
        #pragma unroll
        for (int q = 0; q < 4; q++) {
            float2 f = __half22float2(hp[q]);
            accA[q * 2 + 0] += s * f.x; accA[q * 2 + 1] += s * f.y;
        }
    }
    #pragma unroll
    for (int q = 0; q < 8; q++) accA[q] += accB[q];
    if (grp > 0) {
        #pragma unroll
        for (int q = 0; q < 8; q++) red[grp - 1][l][q] = accA[q];
    }
    __syncthreads();
    if (grp == 0) {
        #pragma unroll
        for (int gq = 0; gq < 7; gq++)
            #pragma unroll
            for (int q = 0; q < 8; q++) accA[q] += red[gq][l][q];
        float4 o0 = make_float4(accA[0], accA[1], accA[2], accA[3]);
        float4 o1 = make_float4(accA[4], accA[5], accA[6], accA[7]);
        ((float4*)out_newh)[(size_t)r * 64 + l * 2 + 0] = o0;
        ((float4*)out_newh)[(size_t)r * 64 + l * 2 + 1] = o1;
    }
}

// ---------------- K7: write g_new directly (membership bit * column rinv) ----------------
__global__ void k_gnew(float* __restrict__ out_gnew) {
    int t = blockIdx.x * blockDim.x + threadIdx.x;
    int r = t >> 11, c = t & (Kk - 1);
    int j = d_idx[c];
    unsigned w = d_bm[r * (Nn / 32) + (j >> 5)];
    out_gnew[t] = ((w >> (j & 31)) & 1u) ? d_rinv[c] : 0.f;
}

// ---------------- launch (fork csr onto side stream; join before rowfeat) ----------------
extern "C" void kernel_launch(void* const* d_in, const int* in_sizes, int n_in,
                              void* d_out, int out_size) {
    const float* g      = (const float*)d_in[0];
    const float* h      = (const float*)d_in[1];
    const float* gamma  = (const float*)d_in[2];
    const float* beta   = (const float*)d_in[3];
    const float* wproj  = (const float*)d_in[4];
    const float* bproj  = (const float*)d_in[5];
    const float* sigma1 = (const float*)d_in[6];

    float* out      = (float*)d_out;
    float* out_gnew = out;                               // Kk*Kk
    float* out_newh = out + (size_t)Kk * Kk;             // Kk*Dd
    float* out_idx  = out_newh + (size_t)Kk * Dd;        // Kk

    // streams/events created once, on the first (non-captured) correctness call
    static cudaStream_t s1 = nullptr;
    static cudaEvent_t  eFork = nullptr, eJoin = nullptr;
    if (s1 == nullptr) {
        cudaStreamCreateWithFlags(&s1, cudaStreamNonBlocking);
        cudaEventCreateWithFlags(&eFork, cudaEventDisableTiming);
        cudaEventCreateWithFlags(&eJoin, cudaEventDisableTiming);
    }

    // fork: csr (g-chain) on s1, h-chain on main stream
    cudaEventRecord(eFork, 0);
    cudaStreamWaitEvent(s1, eFork, 0);
    k_csr<<<Nn / 8, 256, 0, s1>>>(g);
    cudaEventRecord(eJoin, s1);

    k_colstats<<<64, 256>>>(h);
    k_colfin  <<<1, 256>>>(gamma);
    k_norm    <<<(Nn * Dd / 4) / 256, 256>>>(h, beta);

    // join: rowfeat needs both CSR and HN
    cudaStreamWaitEvent(0, eJoin, 0);
    k_rowfeat <<<Nn, 256>>>(wproj, bproj);
    k_topk    <<<1, 1024>>>(sigma1, out_idx);
    k_pool    <<<Kk, 256>>>(out_newh);
    k_gnew    <<<(Kk * Kk) / 256, 256>>>(out_gnew);
}

// round 11
// speedup vs baseline: 1.4634x; 1.0405x over previous
#include <cuda_runtime.h>
#include <cuda_fp16.h>
#include <math.h>

#define Nn 4096
#define Dd 256
#define Kk 2048
#define MAXD 128
#define EPSc 1e-5f

// ---------------- scratch (device globals; no allocation) ----------------
__device__ float  d_HN[Nn * Dd];        // normalized h (fp32, score path)
__device__ __half d_HNh[Nn * Dd];       // fp16 mirror (gather path only)
__device__ float  d_psum[64 * Dd];
__device__ float  d_psq[64 * Dd];
__device__ float  d_mu[Dd];
__device__ float  d_inv[Dd];            // gamma / sqrt(var+eps)
__device__ int    d_nbr[Nn * MAXD];     // CSR neighbor lists (fixed lane-interleaved order)
__device__ int    d_ncnt[Nn];
__device__ float  d_deg[Nn];
__device__ float  d_Z1[Nn];
__device__ float  d_Z3[Nn];
__device__ float  d_PF[Nn];
__device__ float  d_SC[Nn];             // scores
__device__ int    d_idx[Kk];
__device__ unsigned d_selw[Nn / 32];    // bitmask of selected nodes
__device__ unsigned d_bm[Kk * (Nn / 32)]; // per-selected-row two-hop bitmaps (1 MB)
__device__ float  d_rinv[Kk];           // 1 / rowcount(r)

// ---------------- K1: column stats (deterministic 2-stage) ----------------
__global__ void k_colstats(const float* __restrict__ h) {
    int b = blockIdx.x, d = threadIdx.x;
    float s = 0.f, q = 0.f;
    int r0 = b * 64;
    for (int r = 0; r < 64; r++) {
        float v = h[(r0 + r) * Dd + d];
        s += v; q += v * v;
    }
    d_psum[b * Dd + d] = s;
    d_psq [b * Dd + d] = q;
}

__global__ void k_colfin(const float* __restrict__ gamma) {
    int d = threadIdx.x;
    float s = 0.f, q = 0.f;
    for (int b = 0; b < 64; b++) { s += d_psum[b * Dd + d]; q += d_psq[b * Dd + d]; }
    float mu  = s / (float)Nn;
    float var = q / (float)Nn - mu * mu;
    d_mu[d]  = mu;
    d_inv[d] = gamma[d] / sqrtf(var + EPSc);
}

// ---------------- K2: normalize h (float4), write fp32 + fp16 mirror ----------------
__global__ void k_norm(const float* __restrict__ h, const float* __restrict__ beta) {
    int t = blockIdx.x * blockDim.x + threadIdx.x;          // over Nn*Dd/4
    int d4 = t & (Dd / 4 - 1);
    float4 hv = ((const float4*)h)[t];
    float4 mu = ((const float4*)d_mu)[d4];
    float4 iv = ((const float4*)d_inv)[d4];
    float4 be = ((const float4*)beta)[d4];
    float4 o;
    o.x = (hv.x - mu.x) * iv.x + be.x;
    o.y = (hv.y - mu.y) * iv.y + be.y;
    o.z = (hv.z - mu.z) * iv.z + be.z;
    o.w = (hv.w - mu.w) * iv.w + be.w;
    ((float4*)d_HN)[t] = o;
    __half2 p0 = __floats2half2_rn(o.x, o.y);
    __half2 p1 = __floats2half2_rn(o.z, o.w);
    ((__half2*)d_HNh)[t * 2 + 0] = p0;
    ((__half2*)d_HNh)[t * 2 + 1] = p1;
}

// ---------------- K3: CSR from dense binary g (warp/row; per-lane masks + 1 scan/batch) --
__global__ void k_csr(const float* __restrict__ g) {
    int row  = (blockIdx.x * blockDim.x + threadIdx.x) >> 5;
    int lane = threadIdx.x & 31;
    if (row >= Nn) return;
    const float4* r4 = (const float4*)(g + (size_t)row * Nn);
    int cnt = 0;
    for (int b = 0; b < 8; b++) {
        float4 v0 = r4[(b * 4 + 0) * 32 + lane];
        float4 v1 = r4[(b * 4 + 1) * 32 + lane];
        float4 v2 = r4[(b * 4 + 2) * 32 + lane];
        float4 v3 = r4[(b * 4 + 3) * 32 + lane];
        unsigned msk = 0u;
        msk |= (v0.x != 0.f) ? 0x0001u : 0u;  msk |= (v0.y != 0.f) ? 0x0002u : 0u;
        msk |= (v0.z != 0.f) ? 0x0004u : 0u;  msk |= (v0.w != 0.f) ? 0x0008u : 0u;
        msk |= (v1.x != 0.f) ? 0x0010u : 0u;  msk |= (v1.y != 0.f) ? 0x0020u : 0u;
        msk |= (v1.z != 0.f) ? 0x0040u : 0u;  msk |= (v1.w != 0.f) ? 0x0080u : 0u;
        msk |= (v2.x != 0.f) ? 0x0100u : 0u;  msk |= (v2.y != 0.f) ? 0x0200u : 0u;
        msk |= (v2.z != 0.f) ? 0x0400u : 0u;  msk |= (v2.w != 0.f) ? 0x0800u : 0u;
        msk |= (v3.x != 0.f) ? 0x1000u : 0u;  msk |= (v3.y != 0.f) ? 0x2000u : 0u;
        msk |= (v3.z != 0.f) ? 0x4000u : 0u;  msk |= (v3.w != 0.f) ? 0x8000u : 0u;
        int lc = __popc(msk);
        int inc = lc;
        #pragma unroll
        for (int o = 1; o < 32; o <<= 1) {
            int n = __shfl_up_sync(0xffffffffu, inc, o);
            if (lane >= o) inc += n;
        }
        int total = __shfl_sync(0xffffffffu, inc, 31);
        int base = cnt + inc - lc;
        while (msk) {
            int q = __ffs((int)msk) - 1;
            msk &= msk - 1;
            int col = (b * 4 + (q >> 2)) * 128 + lane * 4 + (q & 3);
            if (base < MAXD) d_nbr[row * MAXD + base] = col;
            base++;
        }
        cnt += total;
    }
    if (lane == 0) {
        d_ncnt[row] = cnt < MAXD ? cnt : MAXD;
        d_deg[row]  = (float)cnt;
    }
}

// ---------------- K4: per-row agg, Z1, Z3, pf (single fused 3-value reduction) ----------
__global__ void k_rowfeat(const float* __restrict__ wproj, const float* __restrict__ bproj) {
    int i = blockIdx.x, d = threadIdx.x;
    __shared__ int   snb[MAXD];
    __shared__ float wr[8][3];
    int cnt = d_ncnt[i];
    if (d < cnt) snb[d] = d_nbr[i * MAXD + d];
    __syncthreads();
    float acc = 0.f;
    for (int e = 0; e < cnt; e++) acc += d_HN[snb[e] * Dd + d];
    float agg = acc / d_deg[i];
    float hv  = d_HN[i * Dd + d];
    float w   = wproj[d];
    float a = fabsf(hv - agg), b = agg * w, c = hv * w;
    for (int o = 16; o; o >>= 1) {
        a += __shfl_down_sync(0xffffffffu, a, o);
        b += __shfl_down_sync(0xffffffffu, b, o);
        c += __shfl_down_sync(0xffffffffu, c, o);
    }
    if ((d & 31) == 0) { wr[d >> 5][0] = a; wr[d >> 5][1] = b; wr[d >> 5][2] = c; }
    __syncthreads();
    if (d == 0) {
        float A = 0.f, B = 0.f, C = 0.f;
        for (int k = 0; k < 8; k++) { A += wr[k][0]; B += wr[k][1]; C += wr[k][2]; }
        float bb = bproj[0];
        d_Z1[i] = A;
        d_Z3[i] = B + bb;
        d_PF[i] = 1.f / (1.f + expf(-(C + bb)));
    }
}

// ---------------- K5: fused softmax + scores + top-k bitonic (warp-sync small-j) --------
__global__ void k_topk(const float* __restrict__ sigma1, float* __restrict__ out_idx) {
    __shared__ unsigned long long sk[Nn];
    __shared__ float sh[1024];
    int t = threadIdx.x;

    float mx = -3.4e38f;
    for (int i = t; i < Nn; i += 1024) mx = fmaxf(mx, d_Z3[i]);
    sh[t] = mx; __syncthreads();
    for (int s = 512; s > 0; s >>= 1) { if (t < s) sh[t] = fmaxf(sh[t], sh[t + s]); __syncthreads(); }
    float M = sh[0]; __syncthreads();
    float sm = 0.f;
    for (int i = t; i < Nn; i += 1024) sm += expf(d_Z3[i] - M);
    sh[t] = sm; __syncthreads();
    for (int s = 512; s > 0; s >>= 1) { if (t < s) sh[t] += sh[t + s]; __syncthreads(); }
    float S = sh[0];
    float s1 = sigma1[0];

    for (int i = t; i < Nn; i += 1024) {
        float pg = expf(d_Z3[i] - M) / S;
        float pl = 1.f / (1.f + expf(-(d_Z1[i] + d_deg[i])));
        float pt = 1.f / (1.f + expf(-(pl + pg)));
        float sc = s1 * pt + (1.f - s1) * d_PF[i];
        d_SC[i] = sc;
        unsigned u = __float_as_uint(sc);
        u = (u & 0x80000000u) ? ~u : (u | 0x80000000u);
        sk[i] = ((unsigned long long)(~u) << 32) | (unsigned)i;  // asc key = desc score, asc idx ties
    }
    if (t < Nn / 32) d_selw[t] = 0u;
    __syncthreads();

    // bitonic sort; i and i^j handled by threads t and t^j (same warp when j<32):
    // those substeps only need __syncwarp.
    for (int k = 2; k <= Nn; k <<= 1) {
        for (int j = k >> 1; j > 0; j >>= 1) {
            #pragma unroll
            for (int p = 0; p < 4; p++) {
                int i = t + p * 1024;
                int ixj = i ^ j;
                if (ixj > i) {
                    bool up = ((i & k) == 0);
                    unsigned long long a = sk[i], b = sk[ixj];
                    if ((a > b) == up) { sk[i] = b; sk[ixj] = a; }
                }
            }
            if (j >= 32) __syncthreads(); else __syncwarp();
        }
    }
    __syncthreads();
    for (int c = t; c < Kk; c += 1024) {
        int j = (int)(sk[c] & 0xffffffffULL);
        d_idx[c] = j;
        atomicOr(&d_selw[j >> 5], 1u << (j & 31));
        out_idx[c] = (float)j;
    }
}

// ---------------- K6: per-selected-row two-hop -> new_h (fp16 gather MLP=4), bitmap -----
__global__ void k_pool(float* __restrict__ out_newh) {
    __shared__ unsigned bm[Nn / 32];
    __shared__ int scn[Nn / 32];
    __shared__ int list[Nn];
    __shared__ float red[7][32][8];
    __shared__ int redi[256];
    int r = blockIdx.x, d = threadIdx.x;
    int i = d_idx[r];
    if (d < Nn / 32) bm[d] = 0u;
    __syncthreads();

    // two-hop expansion into bitmap
    int c1 = d_ncnt[i];
    for (int e = d; e < c1; e += 256) {
        int k = d_nbr[i * MAXD + e];
        int c2 = d_ncnt[k];
        const int* nb = &d_nbr[k * MAXD];
        for (int f = 0; f < c2; f++) {
            int j = nb[f];
            atomicOr(&bm[j >> 5], 1u << (j & 31));
        }
    }
    __syncthreads();

    // deterministic ordered extraction via prefix scan over 128 words
    int pc = (d < Nn / 32) ? __popc(bm[d]) : 0;
    if (d < Nn / 32) scn[d] = pc;
    __syncthreads();
    for (int off = 1; off < Nn / 32; off <<= 1) {
        int v = 0;
        if (d < Nn / 32) { v = scn[d]; if (d >= off) v += scn[d - off]; }
        __syncthreads();
        if (d < Nn / 32) scn[d] = v;
        __syncthreads();
    }
    if (d < Nn / 32) {
        int p = scn[d] - pc;
        unsigned v = bm[d];
        while (v) { int b = __ffs((int)v) - 1; v &= v - 1; list[p++] = d * 32 + b; }
        d_bm[r * (Nn / 32) + d] = bm[d];           // persist bitmap for k_gnew
    }
    int csel = (d < Nn / 32) ? __popc(bm[d] & d_selw[d]) : 0;
    redi[d] = csel;
    __syncthreads();
    int m = scn[Nn / 32 - 1];
    for (int s = 128; s > 0; s >>= 1) { if (d < s) redi[d] += redi[d + s]; __syncthreads(); }
    if (d == 0) d_rinv[r] = 1.f / (float)redi[0];

    // new_h[r]: fp16 gather, 8 groups x 32 lanes, 8 dims/lane, unroll-4 (MLP=4)
    int grp = d >> 5, l = d & 31;
    const uint4* H4 = (const uint4*)d_HNh;
    float acc0[8], acc1[8];
    #pragma unroll
    for (int q = 0; q < 8; q++) { acc0[q] = 0.f; acc1[q] = 0.f; }
    int e = grp;
    for (; e + 24 < m; e += 32) {
        int j0 = list[e], j1 = list[e + 8], j2 = list[e + 16], j3 = list[e + 24];
        float s0 = d_SC[j0], s1 = d_SC[j1], s2 = d_SC[j2], s3 = d_SC[j3];
        uint4 va = H4[j0 * 32 + l];
        uint4 vb = H4[j1 * 32 + l];
        uint4 vc = H4[j2 * 32 + l];
        uint4 vd = H4[j3 * 32 + l];
        const __half2* ha = (const __half2*)&va;
        const __half2* hb = (const __half2*)&vb;
        const __half2* hc = (const __half2*)&vc;
        const __half2* hd = (const __half2*)&vd;
        #pragma unroll
        for (int q = 0; q < 4; q++) {
            float2 fa = __half22float2(ha[q]);
            float2 fb = __half22float2(hb[q]);
            float2 fc = __half22float2(hc[q]);
            float2 fd = __half22float2(hd[q]);
            acc0[q * 2 + 0] += s0 * fa.x + s2 * fc.x;
            acc0[q * 2 + 1] += s0 * fa.y + s2 * fc.y;
            acc1[q * 2 + 0] += s1 * fb.x + s3 * fd.x;
            acc1[q * 2 + 1] += s1 * fb.y + s3 * fd.y;
        }
    }
    for (; e < m; e += 8) {
        int j = list[e];
        float s = d_SC[j];
        uint4 v = H4[j * 32 + l];
        const __half2* hp = (const __half2*)&v;
        #pragma unroll
        for (int q = 0; q < 4; q++) {
            float2 f = __half22float2(hp[q]);
            acc0[q * 2 + 0] += s * f.x; acc0[q * 2 + 1] += s * f.y;
        }
    }
    #pragma unroll
    for (int q = 0; q < 8; q++) acc0[q] += acc1[q];
    if (grp > 0) {
        #pragma unroll
        for (int q = 0; q < 8; q++) red[grp - 1][l][q] = acc0[q];
    }
    __syncthreads();
    if (grp == 0) {
        #pragma unroll
        for (int gq = 0; gq < 7; gq++)
            #pragma unroll
            for (int q = 0; q < 8; q++) acc0[q] += red[gq][l][q];
        float4 o0 = make_float4(acc0[0], acc0[1], acc0[2], acc0[3]);
        float4 o1 = make_float4(acc0[4], acc0[5], acc0[6], acc0[7]);
        ((float4*)out_newh)[(size_t)r * 64 + l * 2 + 0] = o0;
        ((float4*)out_newh)[(size_t)r * 64 + l * 2 + 1] = o1;
    }
}

// ---------------- K7: write g_new directly (membership bit * column rinv) ----------------
__global__ void k_gnew(float* __restrict__ out_gnew) {
    int t = blockIdx.x * blockDim.x + threadIdx.x;
    int r = t >> 11, c = t & (Kk - 1);
    int j = d_idx[c];
    unsigned w = d_bm[r * (Nn / 32) + (j >> 5)];
    out_gnew[t] = ((w >> (j & 31)) & 1u) ? d_rinv[c] : 0.f;
}

// ---------------- launch (fork csr onto side stream; join before rowfeat) ----------------
extern "C" void kernel_launch(void* const* d_in, const int* in_sizes, int n_in,
                              void* d_out, int out_size) {
    const float* g      = (const float*)d_in[0];
    const float* h      = (const float*)d_in[1];
    const float* gamma  = (const float*)d_in[2];
    const float* beta   = (const float*)d_in[3];
    const float* wproj  = (const float*)d_in[4];
    const float* bproj  = (const float*)d_in[5];
    const float* sigma1 = (const float*)d_in[6];

    float* out      = (float*)d_out;
    float* out_gnew = out;                               // Kk*Kk
    float* out_newh = out + (size_t)Kk * Kk;             // Kk*Dd
    float* out_idx  = out_newh + (size_t)Kk * Dd;        // Kk

    static cudaStream_t s1 = nullptr;
    static cudaEvent_t  eFork = nullptr, eJoin = nullptr;
    if (s1 == nullptr) {
        cudaStreamCreateWithFlags(&s1, cudaStreamNonBlocking);
        cudaEventCreateWithFlags(&eFork, cudaEventDisableTiming);
        cudaEventCreateWithFlags(&eJoin, cudaEventDisableTiming);
    }

    cudaEventRecord(eFork, 0);
    cudaStreamWaitEvent(s1, eFork, 0);
    k_csr<<<Nn / 8, 256, 0, s1>>>(g);
    cudaEventRecord(eJoin, s1);

    k_colstats<<<64, 256>>>(h);
    k_colfin  <<<1, 256>>>(gamma);
    k_norm    <<<(Nn * Dd / 4) / 256, 256>>>(h, beta);

    cudaStreamWaitEvent(0, eJoin, 0);
    k_rowfeat <<<Nn, 256>>>(wproj, bproj);
    k_topk    <<<1, 1024>>>(sigma1, out_idx);
    k_pool    <<<Kk, 256>>>(out_newh);
    k_gnew    <<<(Kk * Kk) / 256, 256>>>(out_gnew);
}